// round 1
// baseline (speedup 1.0000x reference)
#include <cuda_runtime.h>

// ---------------------------------------------------------------------------
// LinearEmulator: out[p] = prod_l (1 - V[l,p]) * poly(p)
// V = amp * (eta * lorentz + (1-eta) * gauss)   (pseudo-Voigt)
//
// Strategy:
//   1) precomp_kernel: per-line constants (3000 threads, negligible cost)
//        c_lor = amp*eta*gamma/pi          -> lorentz = c_lor / (g2 + d^2)
//        g2    = gamma^2
//        m     = -0.5/sigma^2 * log2(e)    -> gauss exp = 2^(m*d^2)
//        c_g   = amp*(1-eta)/(sigma*2.5066)
//   2) voigt_kernel: pixel-per-thread, lines staged through shared memory
//      tiles (broadcast LDS). Gaussian branch predicated off when
//      m*d^2 < -20 (contribution < 2^-20 * c_g, far below 1e-3 tolerance).
//      Lorentzian computed for every pair (heavy tails matter).
// ---------------------------------------------------------------------------

#define MAX_LINES 4096
#define TILE      1024

__device__ float4 g_A[MAX_LINES];  // {lam, g2, c_lor, m}
__device__ float  g_B[MAX_LINES];  // c_gauss

__global__ void precomp_kernel(const float* __restrict__ lam,
                               const float* __restrict__ amps,
                               const float* __restrict__ sw,
                               const float* __restrict__ gw,
                               int L) {
    int l = blockIdx.x * blockDim.x + threadIdx.x;
    if (l >= L) return;

    float sigma = expf(sw[l]);
    float gamma = expf(gw[l]);
    float fg = 2.3548f * sigma;
    float fl = 2.0f * gamma;

    float fg2 = fg * fg;
    float fl2 = fl * fl;
    float poly = fg2 * fg2 * fg
               + 2.69269f * fg2 * fg2 * fl
               + 2.42843f * fg2 * fg  * fl2
               + 4.47163f * fg2 * fl  * fl2
               + 0.07842f * fg  * fl2 * fl2
               + fl2 * fl2 * fl;
    float fwhm = powf(poly, 0.2f);
    float fr = fl / fwhm;
    float eta = fr * (1.36603f + fr * (-0.47719f + fr * 0.11116f));
    float amp = expf(amps[l]);

    float g2    = gamma * gamma;
    float c_lor = amp * eta * gamma * (1.0f / 3.141592654f);
    float m     = -0.5f / (sigma * sigma) * 1.4426950408889634f; // includes log2(e)
    float c_g   = amp * (1.0f - eta) / (sigma * 2.5066f);

    g_A[l] = make_float4(lam[l], g2, c_lor, m);
    g_B[l] = c_g;
}

__global__ void __launch_bounds__(256)
voigt_kernel(const float* __restrict__ wl,
             int npix, int L,
             const float* __restrict__ pa,
             const float* __restrict__ pb,
             const float* __restrict__ pc,
             float* __restrict__ out) {
    __shared__ float4 sA[TILE];
    __shared__ float  sB[TILE];

    int p = blockIdx.x * blockDim.x + threadIdx.x;
    float wlp = (p < npix) ? wl[p] : 0.0f;
    float prod = 1.0f;

    for (int base = 0; base < L; base += TILE) {
        int cnt = min(TILE, L - base);
        __syncthreads();
        for (int i = threadIdx.x; i < cnt; i += blockDim.x) {
            sA[i] = g_A[base + i];
            sB[i] = g_B[base + i];
        }
        __syncthreads();

        #pragma unroll 4
        for (int j = 0; j < cnt; ++j) {
            float4 a  = sA[j];
            float  cg = sB[j];
            float d   = wlp - a.x;
            float d2  = d * d;
            float den = d2 + a.y;
            float v   = __fdividef(a.z, den);   // MUFU.RCP + FMUL (lorentz part)
            float t   = d2 * a.w;               // negative
            if (t > -20.0f) {                   // gaussian numerically alive
                float e;
                asm("ex2.approx.ftz.f32 %0, %1;" : "=f"(e) : "f"(t));
                v = fmaf(cg, e, v);
            }
            prod = fmaf(-v, prod, prod);        // prod *= (1 - v)
        }
    }

    if (p < npix) {
        float x    = (wlp - 10500.0f) * (1.0f / 2500.0f);
        float poly = pa[0] + (pb[0] + pc[0] * x) * x;
        out[p] = prod * poly;
    }
}

extern "C" void kernel_launch(void* const* d_in, const int* in_sizes, int n_in,
                              void* d_out, int out_size) {
    const float* wl   = (const float*)d_in[0];
    const float* lam  = (const float*)d_in[1];
    const float* amps = (const float*)d_in[2];
    const float* sw   = (const float*)d_in[3];
    const float* gw   = (const float*)d_in[4];
    const float* pa   = (const float*)d_in[5];
    const float* pb   = (const float*)d_in[6];
    const float* pc   = (const float*)d_in[7];
    float* out = (float*)d_out;

    int npix = in_sizes[0];
    int L    = in_sizes[1];

    precomp_kernel<<<(L + 255) / 256, 256>>>(lam, amps, sw, gw, L);
    voigt_kernel<<<(npix + 255) / 256, 256>>>(wl, npix, L, pa, pb, pc, out);
}

// round 2
// speedup vs baseline: 11.1832x; 11.1832x over previous
#include <cuda_runtime.h>

// ---------------------------------------------------------------------------
// out[p] = prod_l (1 - V[l,p]) * poly(p),  V = pseudo-Voigt
//
// Near/far split per 256-pixel chunk (one CTA):
//   near lines (|lam - chunk| <= 8 A): exact product (lorentz + gated gauss)
//   far lines: prod(1-v) ~= exp(-sum v_lorentz); gaussian numerically dead
//              (sigma<=0.5 => dead beyond 3.2 A < 8 A window).
//              S_far evaluated at 4 chunk nodes, cubic Lagrange interpolation.
// Error budget: linearization ~5e-8, interp ~1e-7, well under 1e-3.
// ---------------------------------------------------------------------------

#define MAX_LINES 4096
#define NEAR_CAP  768
#define BLOCK     256
#define WIN       8.0f

__device__ float4 g_A[MAX_LINES];  // {lam, gamma^2, c_lor, m}  (m = -0.5/sig^2 * log2e)
__device__ float  g_B[MAX_LINES];  // c_gauss

__device__ __forceinline__ float frcp(float x) {
    float r; asm("rcp.approx.ftz.f32 %0, %1;" : "=f"(r) : "f"(x)); return r;
}
__device__ __forceinline__ float fex2(float x) {
    float r; asm("ex2.approx.ftz.f32 %0, %1;" : "=f"(r) : "f"(x)); return r;
}

__global__ void precomp_kernel(const float* __restrict__ lam,
                               const float* __restrict__ amps,
                               const float* __restrict__ sw,
                               const float* __restrict__ gw,
                               int L) {
    int l = blockIdx.x * blockDim.x + threadIdx.x;
    if (l >= L) return;

    float sigma = expf(sw[l]);
    float gamma = expf(gw[l]);
    float fg = 2.3548f * sigma;
    float fl = 2.0f * gamma;

    float fg2 = fg * fg;
    float fl2 = fl * fl;
    float poly = fg2 * fg2 * fg
               + 2.69269f * fg2 * fg2 * fl
               + 2.42843f * fg2 * fg  * fl2
               + 4.47163f * fg2 * fl  * fl2
               + 0.07842f * fg  * fl2 * fl2
               + fl2 * fl2 * fl;
    float fwhm = powf(poly, 0.2f);
    float fr = fl / fwhm;
    float eta = fr * (1.36603f + fr * (-0.47719f + fr * 0.11116f));
    float amp = expf(amps[l]);

    g_A[l] = make_float4(lam[l],
                         gamma * gamma,
                         amp * eta * gamma * (1.0f / 3.141592654f),
                         -0.5f / (sigma * sigma) * 1.4426950408889634f);
    g_B[l] = amp * (1.0f - eta) / (sigma * 2.5066f);
}

__global__ void __launch_bounds__(BLOCK)
voigt_split_kernel(const float* __restrict__ wl, int npix, int L,
                   const float* __restrict__ pa,
                   const float* __restrict__ pb,
                   const float* __restrict__ pc,
                   float* __restrict__ out) {
    __shared__ float4 sNA[NEAR_CAP];
    __shared__ float  sNB[NEAR_CAP];
    __shared__ float  sNode[4];
    __shared__ float  sS[4];
    __shared__ float  sWred[32];
    __shared__ int    sCnt;

    const int tid = threadIdx.x;
    const int p0  = blockIdx.x * BLOCK;
    const int cnt = min(BLOCK, npix - p0);
    const int p   = p0 + tid;

    if (tid == 0) sCnt = 0;
    const int j1 = (cnt - 1) / 3;
    const int j2 = (2 * (cnt - 1)) / 3;
    const int j3 = cnt - 1;
    if (tid < 4) {
        int jj = (tid == 0) ? 0 : (tid == 1) ? j1 : (tid == 2) ? j2 : j3;
        sNode[tid] = wl[p0 + jj];
    }
    __syncthreads();

    const float n0 = sNode[0], n1 = sNode[1], n2 = sNode[2], n3 = sNode[3];
    const float xlo = n0 - WIN, xhi = n3 + WIN;

    // Single pass over all lines: compact near lines to smem, accumulate far
    // lorentzian sums at the 4 nodes.
    float S0 = 0.f, S1 = 0.f, S2 = 0.f, S3 = 0.f;
    for (int l = tid; l < L; l += BLOCK) {
        float4 A = g_A[l];
        if (A.x >= xlo && A.x <= xhi) {
            int pos = atomicAdd(&sCnt, 1);
            if (pos < NEAR_CAP) { sNA[pos] = A; sNB[pos] = g_B[l]; }
        } else {
            float d;
            d = n0 - A.x; S0 = fmaf(A.z, frcp(fmaf(d, d, A.y)), S0);
            d = n1 - A.x; S1 = fmaf(A.z, frcp(fmaf(d, d, A.y)), S1);
            d = n2 - A.x; S2 = fmaf(A.z, frcp(fmaf(d, d, A.y)), S2);
            d = n3 - A.x; S3 = fmaf(A.z, frcp(fmaf(d, d, A.y)), S3);
        }
    }

    // Block reduction of the 4 node sums.
    #pragma unroll
    for (int o = 16; o; o >>= 1) {
        S0 += __shfl_xor_sync(0xFFFFFFFFu, S0, o);
        S1 += __shfl_xor_sync(0xFFFFFFFFu, S1, o);
        S2 += __shfl_xor_sync(0xFFFFFFFFu, S2, o);
        S3 += __shfl_xor_sync(0xFFFFFFFFu, S3, o);
    }
    const int wid = tid >> 5, lane = tid & 31;
    if (lane == 0) {
        sWred[wid]      = S0;
        sWred[8 + wid]  = S1;
        sWred[16 + wid] = S2;
        sWred[24 + wid] = S3;
    }
    __syncthreads();
    if (tid < 4) {
        float s = 0.f;
        #pragma unroll
        for (int w = 0; w < 8; w++) s += sWred[tid * 8 + w];
        sS[tid] = s;
    }
    __syncthreads();

    // Near-field exact product.
    const int nc = min(sCnt, NEAR_CAP);
    const float wlp = wl[min(p, npix - 1)];
    float prod = 1.0f;
    for (int j = 0; j < nc; ++j) {
        float4 a  = sNA[j];
        float  cg = sNB[j];
        float d   = wlp - a.x;
        float d2  = d * d;
        float v   = a.z * frcp(d2 + a.y);
        float t   = d2 * a.w;
        if (t > -20.0f) v = fmaf(cg, fex2(t), v);
        prod = fmaf(-v, prod, prod);
    }

    if (p < npix) {
        // Cubic Lagrange interpolation of S_far at u = pixel offset in chunk.
        float u  = (float)tid;
        float f1 = (float)j1, f2 = (float)j2, f3 = (float)j3;
        float u0 = u, u1 = u - f1, u2 = u - f2, u3 = u - f3;
        float w0 = (u1 * u2 * u3) / ((-f1) * (-f2) * (-f3));
        float w1 = (u0 * u2 * u3) / (f1 * (f1 - f2) * (f1 - f3));
        float w2 = (u0 * u1 * u3) / (f2 * (f2 - f1) * (f2 - f3));
        float w3 = (u0 * u1 * u2) / (f3 * (f3 - f1) * (f3 - f2));
        float Sfar = w0 * sS[0] + w1 * sS[1] + w2 * sS[2] + w3 * sS[3];

        float x    = (wlp - 10500.0f) * (1.0f / 2500.0f);
        float poly = pa[0] + (pb[0] + pc[0] * x) * x;
        out[p] = prod * __expf(-Sfar) * poly;
    }
}

extern "C" void kernel_launch(void* const* d_in, const int* in_sizes, int n_in,
                              void* d_out, int out_size) {
    const float* wl   = (const float*)d_in[0];
    const float* lam  = (const float*)d_in[1];
    const float* amps = (const float*)d_in[2];
    const float* sw   = (const float*)d_in[3];
    const float* gw   = (const float*)d_in[4];
    const float* pa   = (const float*)d_in[5];
    const float* pb   = (const float*)d_in[6];
    const float* pc   = (const float*)d_in[7];
    float* out = (float*)d_out;

    int npix = in_sizes[0];
    int L    = in_sizes[1];

    precomp_kernel<<<(L + 255) / 256, 256>>>(lam, amps, sw, gw, L);
    voigt_split_kernel<<<(npix + BLOCK - 1) / BLOCK, BLOCK>>>(wl, npix, L, pa, pb, pc, out);
}